// round 1
// baseline (speedup 1.0000x reference)
#include <cuda_runtime.h>
#include <cuda_bf16.h>
#include <cstdint>

#define SEQ    2048
#define BATCH  64
#define IN_DIM 512
#define HID    512
#define NGATE  2048   // 4*HID, packed n = j*4 + gate  (gate: 0=f,1=i,2=g,3=o)

// ---------------- scratch (device globals: the sanctioned scratch path) ----
__device__ float g_Wx[IN_DIM * NGATE];                    // 4 MB
__device__ float g_Wh[HID * NGATE];                       // 4 MB
__device__ float g_bias[NGATE];
__device__ float g_pre[(size_t)SEQ * BATCH * NGATE];      // 1 GiB
__device__ float g_h[2][BATCH * HID];                     // double-buffered h
__device__ unsigned g_bar_count;
__device__ volatile unsigned g_bar_gen;

// ---------------- helpers --------------------------------------------------
__device__ __forceinline__ float to_tf32(float x) {
    uint32_t y;
    asm("cvt.rna.tf32.f32 %0, %1;" : "=r"(y) : "f"(x));
    return __uint_as_float(y);
}

__device__ __forceinline__ void mma_tf32(float c[4],
                                         uint32_t a0, uint32_t a1, uint32_t a2, uint32_t a3,
                                         uint32_t b0, uint32_t b1) {
    asm("mma.sync.aligned.m16n8k8.row.col.f32.tf32.tf32.f32 "
        "{%0,%1,%2,%3}, {%4,%5,%6,%7}, {%8,%9}, {%0,%1,%2,%3};"
        : "+f"(c[0]), "+f"(c[1]), "+f"(c[2]), "+f"(c[3])
        : "r"(a0), "r"(a1), "r"(a2), "r"(a3), "r"(b0), "r"(b1));
}

__device__ __forceinline__ float sigm(float x) { return 1.0f / (1.0f + expf(-x)); }

// ---------------- prep: pack weights into gate-interleaved layout ----------
__global__ void prep_kernel(const float* __restrict__ Wf, const float* __restrict__ bf,
                            const float* __restrict__ Wi, const float* __restrict__ bi,
                            const float* __restrict__ Wg, const float* __restrict__ bg,
                            const float* __restrict__ Wo, const float* __restrict__ bo) {
    int idx = blockIdx.x * blockDim.x + threadIdx.x;   // over 1024*512 (k, j)
    if (idx < (IN_DIM + HID) * HID) {
        int k = idx / HID;
        int j = idx % HID;
        const float* Wlist[4] = {Wf, Wi, Wg, Wo};
#pragma unroll
        for (int g = 0; g < 4; g++) {
            float w = Wlist[g][(size_t)k * HID + j];
            int n = j * 4 + g;
            if (k < IN_DIM) g_Wx[(size_t)k * NGATE + n] = w;
            else            g_Wh[(size_t)(k - IN_DIM) * NGATE + n] = w;
        }
    }
    if (idx < HID) {
        const float* blist[4] = {bf, bi, bg, bo};
#pragma unroll
        for (int g = 0; g < 4; g++) g_bias[idx * 4 + g] = blist[g][idx];
    }
}

// ---------------- phase 1: pre = X @ Wx + bias  (tf32 mma GEMM) ------------
// M = SEQ*BATCH = 131072, K = 512, N = 2048. Block tile 128x64, BK=32,
// 8 warps (4x2), warp tile 32x32, mma m16n8k8.
__global__ __launch_bounds__(256) void gemm_pre_kernel(const float* __restrict__ X) {
    __shared__ float As[32][132];   // [k][m], padded
    __shared__ float Bs[32][68];    // [k][n], padded

    const int tid  = threadIdx.x;
    const int lane = tid & 31;
    const int warp = tid >> 5;
    const int m0 = blockIdx.x * 128;
    const int n0 = blockIdx.y * 64;
    const int wm = (warp >> 1) * 32;
    const int wn = (warp & 1) * 32;

    const int arow = tid >> 3;          // 0..31
    const int acol = (tid & 7) * 4;     // k offset within tile
    const int brow = tid >> 4;          // 0..15
    const int bcol = (tid & 15) * 4;

    float acc[2][4][4];
#pragma unroll
    for (int i = 0; i < 2; i++)
#pragma unroll
        for (int j = 0; j < 4; j++)
#pragma unroll
            for (int l = 0; l < 4; l++) acc[i][j][l] = 0.0f;

    float4 ar[4], br[2];

    // prologue load kt=0
#pragma unroll
    for (int p = 0; p < 4; p++)
        ar[p] = *(const float4*)&X[(size_t)(m0 + p * 32 + arow) * IN_DIM + acol];
#pragma unroll
    for (int p = 0; p < 2; p++)
        br[p] = *(const float4*)&g_Wx[(size_t)(p * 16 + brow) * NGATE + n0 + bcol];

#pragma unroll
    for (int p = 0; p < 4; p++) {
        As[acol + 0][p * 32 + arow] = to_tf32(ar[p].x);
        As[acol + 1][p * 32 + arow] = to_tf32(ar[p].y);
        As[acol + 2][p * 32 + arow] = to_tf32(ar[p].z);
        As[acol + 3][p * 32 + arow] = to_tf32(ar[p].w);
    }
#pragma unroll
    for (int p = 0; p < 2; p++) {
        float4 v;
        v.x = to_tf32(br[p].x); v.y = to_tf32(br[p].y);
        v.z = to_tf32(br[p].z); v.w = to_tf32(br[p].w);
        *(float4*)&Bs[p * 16 + brow][bcol] = v;
    }
    __syncthreads();

    for (int kt = 0; kt < 16; kt++) {
        if (kt < 15) {
            int kb = (kt + 1) * 32;
#pragma unroll
            for (int p = 0; p < 4; p++)
                ar[p] = *(const float4*)&X[(size_t)(m0 + p * 32 + arow) * IN_DIM + kb + acol];
#pragma unroll
            for (int p = 0; p < 2; p++)
                br[p] = *(const float4*)&g_Wx[(size_t)(kb + p * 16 + brow) * NGATE + n0 + bcol];
        }
#pragma unroll
        for (int ks = 0; ks < 4; ks++) {
            const int k = ks * 8;
            uint32_t a[2][4], b[4][2];
#pragma unroll
            for (int mi = 0; mi < 2; mi++) {
                int m = wm + mi * 16 + (lane >> 2);
                a[mi][0] = __float_as_uint(As[k + (lane & 3)][m]);
                a[mi][1] = __float_as_uint(As[k + (lane & 3)][m + 8]);
                a[mi][2] = __float_as_uint(As[k + 4 + (lane & 3)][m]);
                a[mi][3] = __float_as_uint(As[k + 4 + (lane & 3)][m + 8]);
            }
#pragma unroll
            for (int ni = 0; ni < 4; ni++) {
                int n = wn + ni * 8 + (lane >> 2);
                b[ni][0] = __float_as_uint(Bs[k + (lane & 3)][n]);
                b[ni][1] = __float_as_uint(Bs[k + 4 + (lane & 3)][n]);
            }
#pragma unroll
            for (int mi = 0; mi < 2; mi++)
#pragma unroll
                for (int ni = 0; ni < 4; ni++)
                    mma_tf32(acc[mi][ni], a[mi][0], a[mi][1], a[mi][2], a[mi][3],
                             b[ni][0], b[ni][1]);
        }
        __syncthreads();
        if (kt < 15) {
#pragma unroll
            for (int p = 0; p < 4; p++) {
                As[acol + 0][p * 32 + arow] = to_tf32(ar[p].x);
                As[acol + 1][p * 32 + arow] = to_tf32(ar[p].y);
                As[acol + 2][p * 32 + arow] = to_tf32(ar[p].z);
                As[acol + 3][p * 32 + arow] = to_tf32(ar[p].w);
            }
#pragma unroll
            for (int p = 0; p < 2; p++) {
                float4 v;
                v.x = to_tf32(br[p].x); v.y = to_tf32(br[p].y);
                v.z = to_tf32(br[p].z); v.w = to_tf32(br[p].w);
                *(float4*)&Bs[p * 16 + brow][bcol] = v;
            }
            __syncthreads();
        }
    }

    // epilogue: add bias, store
#pragma unroll
    for (int mi = 0; mi < 2; mi++) {
        size_t r = (size_t)(m0 + wm + mi * 16 + (lane >> 2));
#pragma unroll
        for (int ni = 0; ni < 4; ni++) {
            int c = n0 + wn + ni * 8 + 2 * (lane & 3);
            float b0 = g_bias[c], b1 = g_bias[c + 1];
            float2 v0 = make_float2(acc[mi][ni][0] + b0, acc[mi][ni][1] + b1);
            float2 v1 = make_float2(acc[mi][ni][2] + b0, acc[mi][ni][3] + b1);
            *(float2*)&g_pre[r * NGATE + c]       = v0;
            *(float2*)&g_pre[(r + 8) * NGATE + c] = v1;
        }
    }
}

// ---------------- phase 2: persistent recurrence ---------------------------
// 128 CTAs = 4 batch-groups (16 rows) x 32 j-tiles (16 hidden units = 64 gate cols).
// Wh slice resident in SMEM (tf32). Per step: stage h (L2, bypass L1) + pre,
// tf32 mma 16x64x512, fused LSTM elementwise via shfl, grid barrier.
#define P2_NBLK 128

__global__ __launch_bounds__(128) void lstm_rec_kernel(float* __restrict__ out, int write_tail) {
    extern __shared__ float smem[];
    float* Ws = smem;               // [512][66]
    float* hs = Ws + 512 * 66;      // [16][520]
    float* ps = hs + 16 * 520;      // [16][68]
    float* os = ps + 16 * 68;       // [16][17]

    const int tid  = threadIdx.x;
    const int lane = tid & 31;
    const int w    = tid >> 5;                 // warp 0..3 -> 16 gate-cols each
    const int jt   = blockIdx.x & 31;          // j-tile
    const int bg   = blockIdx.x >> 5;          // batch group
    const int row0 = bg * 16;
    const int nc0  = jt * 64;

    // load weight slice once (tf32)
    for (int idx = tid; idx < 512 * 64; idx += 128) {
        int k = idx >> 6, c = idx & 63;
        Ws[k * 66 + c] = to_tf32(g_Wh[(size_t)k * NGATE + nc0 + c]);
    }

    const int  g4   = lane >> 2;               // groupID 0..7
    const int  q    = lane & 3;
    const bool isev = (q & 1) == 0;            // even q holds (f,i); odd holds (g,o)

    float cst[2][2] = {{0.f, 0.f}, {0.f, 0.f}};   // cell state [ni][row r / r+8]

    for (int t = 0; t < SEQ; t++) {
        // stage h (bypass L1: written by other SMs last step)
        if (t == 0) {
            for (int idx = tid; idx < 16 * 512; idx += 128) {
                int r = idx >> 9, k = idx & 511;
                hs[r * 520 + k] = 0.0f;
            }
        } else {
            const float* hp = g_h[t & 1];
            for (int idx = tid; idx < 16 * 512; idx += 128) {
                int r = idx >> 9, k = idx & 511;
                hs[r * 520 + k] = to_tf32(__ldcg(&hp[(row0 + r) * HID + k]));
            }
        }
        {
            const float* pp = g_pre + ((size_t)t * BATCH + row0) * NGATE + nc0;
            for (int idx = tid; idx < 16 * 64; idx += 128) {
                int r = idx >> 6, c = idx & 63;
                ps[r * 68 + c] = __ldg(&pp[(size_t)r * NGATE + c]);
            }
        }
        __syncthreads();

        float acc[2][4] = {{0.f, 0.f, 0.f, 0.f}, {0.f, 0.f, 0.f, 0.f}};
#pragma unroll 8
        for (int kk = 0; kk < 64; kk++) {
            const int k = kk * 8;
            uint32_t a0 = __float_as_uint(hs[g4 * 520 + k + q]);
            uint32_t a1 = __float_as_uint(hs[(g4 + 8) * 520 + k + q]);
            uint32_t a2 = __float_as_uint(hs[g4 * 520 + k + 4 + q]);
            uint32_t a3 = __float_as_uint(hs[(g4 + 8) * 520 + k + 4 + q]);
#pragma unroll
            for (int ni = 0; ni < 2; ni++) {
                int col = w * 16 + ni * 8 + g4;
                uint32_t b0 = __float_as_uint(Ws[(k + q) * 66 + col]);
                uint32_t b1 = __float_as_uint(Ws[(k + 4 + q) * 66 + col]);
                mma_tf32(acc[ni], a0, a1, a2, a3, b0, b1);
            }
        }

        // fused LSTM elementwise: gates of one j sit in adjacent q lanes
#pragma unroll
        for (int ni = 0; ni < 2; ni++) {
            int nl = w * 16 + ni * 8 + 2 * q;
            float v0 = acc[ni][0] + ps[g4 * 68 + nl];
            float v1 = acc[ni][1] + ps[g4 * 68 + nl + 1];
            float v2 = acc[ni][2] + ps[(g4 + 8) * 68 + nl];
            float v3 = acc[ni][3] + ps[(g4 + 8) * 68 + nl + 1];
            // even lanes: (f,i) -> sigmoid,sigmoid ; odd lanes: (g,o) -> tanh,sigmoid
            float e0 = isev ? sigm(v0) : tanhf(v0);
            float e1 = sigm(v1);
            float e2 = isev ? sigm(v2) : tanhf(v2);
            float e3 = sigm(v3);
            float p0 = __shfl_xor_sync(0xffffffffu, e0, 1);
            float p1 = __shfl_xor_sync(0xffffffffu, e1, 1);
            float p2 = __shfl_xor_sync(0xffffffffu, e2, 1);
            float p3 = __shfl_xor_sync(0xffffffffu, e3, 1);
            if (isev) {
                float c0 = e0 * cst[ni][0] + e1 * p0;   // f*c + i*g   (row r)
                float c1 = e2 * cst[ni][1] + e3 * p2;   // (row r+8)
                cst[ni][0] = c0;
                cst[ni][1] = c1;
                float h0 = p1 * tanhf(c0);              // o * tanh(c)
                float h1 = p3 * tanhf(c1);
                int jl = w * 4 + ni * 2 + (q >> 1);
                os[g4 * 17 + jl]       = h0;
                os[(g4 + 8) * 17 + jl] = h1;
            }
        }
        __syncthreads();

        // write out[t] and next h buffer (coalesced 64B rows)
        {
            float* hn = g_h[(t + 1) & 1];
            float* op = out + ((size_t)t * BATCH + row0) * HID + jt * 16;
#pragma unroll
            for (int idx = tid; idx < 256; idx += 128) {
                int r = idx >> 4, j = idx & 15;
                float v = os[r * 17 + j];
                op[(size_t)r * HID + j] = v;
                hn[(row0 + r) * HID + jt * 16 + j] = v;
            }
        }

        // grid barrier (sense-reversing)
        __threadfence();
        __syncthreads();
        if (tid == 0) {
            unsigned gen = g_bar_gen;
            unsigned arrived = atomicAdd(&g_bar_count, 1u);
            if (arrived == (unsigned)(P2_NBLK - 1)) {
                g_bar_count = 0u;
                __threadfence();
                g_bar_gen = gen + 1u;
            } else {
                while (g_bar_gen == gen) { }
            }
            __threadfence();
        }
        __syncthreads();
    }

    if (write_tail) {
        float* hx = out + (size_t)SEQ * BATCH * HID;
        float* cx = hx + BATCH * HID;
        // hx = final h (still in os)
        for (int idx = tid; idx < 256; idx += 128) {
            int r = idx >> 4, j = idx & 15;
            hx[(row0 + r) * HID + jt * 16 + j] = os[r * 17 + j];
        }
        __syncthreads();
        // stage c into os, then write cx
#pragma unroll
        for (int ni = 0; ni < 2; ni++) {
            if (isev) {
                int jl = w * 4 + ni * 2 + (q >> 1);
                os[g4 * 17 + jl]       = cst[ni][0];
                os[(g4 + 8) * 17 + jl] = cst[ni][1];
            }
        }
        __syncthreads();
        for (int idx = tid; idx < 256; idx += 128) {
            int r = idx >> 4, j = idx & 15;
            cx[(row0 + r) * HID + jt * 16 + j] = os[r * 17 + j];
        }
    }
}

// ---------------- launch ---------------------------------------------------
extern "C" void kernel_launch(void* const* d_in, const int* in_sizes, int n_in,
                              void* d_out, int out_size) {
    const float* X  = (const float*)d_in[0];
    const float* Wf = (const float*)d_in[1];
    const float* bf = (const float*)d_in[2];
    const float* Wi = (const float*)d_in[3];
    const float* bi = (const float*)d_in[4];
    const float* Wg = (const float*)d_in[5];
    const float* bg = (const float*)d_in[6];
    const float* Wo = (const float*)d_in[7];
    const float* bo = (const float*)d_in[8];
    float* out = (float*)d_out;

    prep_kernel<<<((IN_DIM + HID) * HID + 255) / 256, 256>>>(Wf, bf, Wi, bi, Wg, bg, Wo, bo);

    dim3 g1(SEQ * BATCH / 128, NGATE / 64);
    gemm_pre_kernel<<<g1, 256>>>(X);

    const int smem2 = (512 * 66 + 16 * 520 + 16 * 68 + 16 * 17) * (int)sizeof(float);
    cudaFuncSetAttribute(lstm_rec_kernel, cudaFuncAttributeMaxDynamicSharedMemorySize, smem2);
    int tail = (out_size >= SEQ * BATCH * HID + 2 * BATCH * HID) ? 1 : 0;
    lstm_rec_kernel<<<P2_NBLK, 128, smem2>>>(out, tail);
}

// round 2
// speedup vs baseline: 2.8097x; 2.8097x over previous
#include <cuda_runtime.h>
#include <cstdint>

#define SEQ    2048
#define BATCH  64
#define IN_DIM 512
#define HID    512
#define NGATE  2048   // 4*HID, packed n = j*4 + gate (0=f,1=i,2=g,3=o)

// ---------------- device-global scratch ------------------------------------
__device__ float g_Wx[IN_DIM * NGATE];                    // 4 MB, tf32-rounded
__device__ float g_Wh[HID * NGATE];                       // 4 MB, tf32-rounded
__device__ float g_bias[NGATE];
__device__ float g_Xr[(size_t)SEQ * BATCH * IN_DIM];      // 256 MB, tf32-rounded
__device__ float g_pre[(size_t)SEQ * BATCH * NGATE];      // 1 GiB
__device__ float g_h[2][BATCH * HID];                     // double-buffered h (tf32-rounded)
__device__ unsigned g_cnt[4 * 32];                        // per-batch-group arrival counters (padded)

// ---------------- helpers --------------------------------------------------
__device__ __forceinline__ float to_tf32(float x) {
    uint32_t y;
    asm("cvt.rna.tf32.f32 %0, %1;" : "=r"(y) : "f"(x));
    return __uint_as_float(y);
}

__device__ __forceinline__ void mma_tf32(float c[4],
                                         uint32_t a0, uint32_t a1, uint32_t a2, uint32_t a3,
                                         uint32_t b0, uint32_t b1) {
    asm("mma.sync.aligned.m16n8k8.row.col.f32.tf32.tf32.f32 "
        "{%0,%1,%2,%3}, {%4,%5,%6,%7}, {%8,%9}, {%0,%1,%2,%3};"
        : "+f"(c[0]), "+f"(c[1]), "+f"(c[2]), "+f"(c[3])
        : "r"(a0), "r"(a1), "r"(a2), "r"(a3), "r"(b0), "r"(b1));
}

__device__ __forceinline__ float tfast(float x) {
    float y;
    asm("tanh.approx.f32 %0, %1;" : "=f"(y) : "f"(x));
    return y;
}
__device__ __forceinline__ float sfast(float x) {          // sigmoid via MUFU tanh
    return fmaf(tfast(x * 0.5f), 0.5f, 0.5f);
}

__device__ __forceinline__ uint32_t smem_u32(const void* p) {
    return (uint32_t)__cvta_generic_to_shared(p);
}
__device__ __forceinline__ void cp16(uint32_t dst, const void* src) {
    asm volatile("cp.async.cg.shared.global [%0], [%1], 16;" :: "r"(dst), "l"(src));
}
#define CP_COMMIT() asm volatile("cp.async.commit_group;")
template <int N>
__device__ __forceinline__ void cp_wait() {
    asm volatile("cp.async.wait_group %0;" :: "n"(N));
}

// ---------------- reset (per-launch) ---------------------------------------
__global__ void reset_kernel() {
    if (threadIdx.x < 4 * 32) g_cnt[threadIdx.x] = 0u;
}

// ---------------- prep: pack + tf32-round weights --------------------------
__global__ void prep_kernel(const float* __restrict__ Wf, const float* __restrict__ bf,
                            const float* __restrict__ Wi, const float* __restrict__ bi,
                            const float* __restrict__ Wg, const float* __restrict__ bg,
                            const float* __restrict__ Wo, const float* __restrict__ bo) {
    int idx = blockIdx.x * blockDim.x + threadIdx.x;
    if (idx < (IN_DIM + HID) * HID) {
        int k = idx / HID;
        int j = idx % HID;
        const float* Wlist[4] = {Wf, Wi, Wg, Wo};
#pragma unroll
        for (int g = 0; g < 4; g++) {
            float w = to_tf32(Wlist[g][(size_t)k * HID + j]);
            int n = j * 4 + g;
            if (k < IN_DIM) g_Wx[(size_t)k * NGATE + n] = w;
            else            g_Wh[(size_t)(k - IN_DIM) * NGATE + n] = w;
        }
    }
    if (idx < HID) {
        const float* blist[4] = {bf, bi, bg, bo};
#pragma unroll
        for (int g = 0; g < 4; g++) g_bias[idx * 4 + g] = blist[g][idx];
    }
}

// ---------------- round X to tf32 ------------------------------------------
__global__ void roundx_kernel(const float* __restrict__ X) {
    const size_t n4 = (size_t)SEQ * BATCH * IN_DIM / 4;
    const float4* src = (const float4*)X;
    float4* dst = (float4*)g_Xr;
    for (size_t i = blockIdx.x * blockDim.x + threadIdx.x; i < n4;
         i += (size_t)gridDim.x * blockDim.x) {
        float4 v = src[i];
        v.x = to_tf32(v.x); v.y = to_tf32(v.y);
        v.z = to_tf32(v.z); v.w = to_tf32(v.w);
        dst[i] = v;
    }
}

// ---------------- phase 1: pre = Xr @ Wx + bias ----------------------------
// CTA tile 256x128, BK=32, 3-stage cp.async, 8 warps (4m x 2n), warp 64x64.
#define GA_ST (256 * 36)
#define GB_ST (32 * 136)

__device__ __forceinline__ void gemm_load_stage(float* As, float* Bs,
                                                int m0, int n0, int kb, int tid) {
#pragma unroll
    for (int i = 0; i < 8; i++) {
        int c = i * 256 + tid;
        int row = c >> 3, col = c & 7;
        cp16(smem_u32(As + row * 36 + col * 4),
             g_Xr + (size_t)(m0 + row) * IN_DIM + kb + col * 4);
    }
#pragma unroll
    for (int i = 0; i < 4; i++) {
        int c = i * 256 + tid;
        int k = c >> 5, n16 = c & 31;
        cp16(smem_u32(Bs + k * 136 + n16 * 4),
             g_Wx + (size_t)(kb + k) * NGATE + n0 + n16 * 4);
    }
}

__global__ __launch_bounds__(256, 1) void gemm_pre_kernel() {
    extern __shared__ float sm[];
    float* As[3] = {sm, sm + GA_ST, sm + 2 * GA_ST};
    float* Bs[3] = {sm + 3 * GA_ST, sm + 3 * GA_ST + GB_ST, sm + 3 * GA_ST + 2 * GB_ST};

    const int tid  = threadIdx.x;
    const int lane = tid & 31;
    const int warp = tid >> 5;
    const int g4   = lane >> 2;
    const int q    = lane & 3;
    const int m0 = blockIdx.y * 256;
    const int n0 = blockIdx.x * 128;       // n fast -> X reuse in L2
    const int wm = (warp >> 1) * 64;
    const int wn = (warp & 1) * 64;

    float acc[4][8][4];
#pragma unroll
    for (int mi = 0; mi < 4; mi++)
#pragma unroll
        for (int ni = 0; ni < 8; ni++)
#pragma unroll
            for (int l = 0; l < 4; l++) acc[mi][ni][l] = 0.0f;

    gemm_load_stage(As[0], Bs[0], m0, n0, 0, tid);  CP_COMMIT();
    gemm_load_stage(As[1], Bs[1], m0, n0, 32, tid); CP_COMMIT();

    for (int kt = 0; kt < 16; kt++) {
        if (kt + 2 < 16) {
            gemm_load_stage(As[(kt + 2) % 3], Bs[(kt + 2) % 3], m0, n0, (kt + 2) * 32, tid);
            CP_COMMIT();
        }
        if (kt <= 13)      cp_wait<2>();
        else if (kt == 14) cp_wait<1>();
        else               cp_wait<0>();
        __syncthreads();

        const float* A = As[kt % 3];
        const float* B = Bs[kt % 3];
#pragma unroll
        for (int ks = 0; ks < 4; ks++) {
            const int kl = ks * 8;
            uint32_t a[4][4], b[8][2];
#pragma unroll
            for (int mi = 0; mi < 4; mi++) {
                int mr = wm + mi * 16 + g4;
                a[mi][0] = __float_as_uint(A[mr * 36 + kl + q]);
                a[mi][1] = __float_as_uint(A[(mr + 8) * 36 + kl + q]);
                a[mi][2] = __float_as_uint(A[mr * 36 + kl + 4 + q]);
                a[mi][3] = __float_as_uint(A[(mr + 8) * 36 + kl + 4 + q]);
            }
#pragma unroll
            for (int ni = 0; ni < 8; ni++) {
                int cn = wn + ni * 8 + g4;
                b[ni][0] = __float_as_uint(B[(kl + q) * 136 + cn]);
                b[ni][1] = __float_as_uint(B[(kl + 4 + q) * 136 + cn]);
            }
#pragma unroll
            for (int mi = 0; mi < 4; mi++)
#pragma unroll
                for (int ni = 0; ni < 8; ni++)
                    mma_tf32(acc[mi][ni], a[mi][0], a[mi][1], a[mi][2], a[mi][3],
                             b[ni][0], b[ni][1]);
        }
        __syncthreads();
    }

    // epilogue: bias + store
    float2 bb[8];
#pragma unroll
    for (int ni = 0; ni < 8; ni++)
        bb[ni] = *(const float2*)&g_bias[n0 + wn + ni * 8 + 2 * q];
#pragma unroll
    for (int mi = 0; mi < 4; mi++) {
        size_t r = (size_t)(m0 + wm + mi * 16 + g4);
#pragma unroll
        for (int ni = 0; ni < 8; ni++) {
            int c = n0 + wn + ni * 8 + 2 * q;
            float2 v0 = make_float2(acc[mi][ni][0] + bb[ni].x, acc[mi][ni][1] + bb[ni].y);
            float2 v1 = make_float2(acc[mi][ni][2] + bb[ni].x, acc[mi][ni][3] + bb[ni].y);
            *(float2*)&g_pre[r * NGATE + c]       = v0;
            *(float2*)&g_pre[(r + 8) * NGATE + c] = v1;
        }
    }
}

// ---------------- phase 2: persistent recurrence ---------------------------
// 128 CTAs = 4 bg(16 rows) x 32 jt(64 gate-cols). Conflict-free smem,
// cp.async staging, per-bg monotonic counter sync, MUFU activations.
#define HS_S 516
#define WS_S 72
#define PS_S 72

__global__ __launch_bounds__(128, 1) void lstm_rec_kernel(float* __restrict__ out, int write_tail) {
    extern __shared__ float sm[];
    float* Ws  = sm;                          // [512][72]
    float* hs  = Ws + 512 * WS_S;             // [16][516]
    float* psm = hs + 16 * HS_S;              // [2][16][72]
    float* os  = psm + 2 * 16 * PS_S;         // [16][17]

    const int tid  = threadIdx.x;
    const int lane = tid & 31;
    const int w    = tid >> 5;
    const int jt   = blockIdx.x & 31;
    const int bg   = blockIdx.x >> 5;
    const int row0 = bg * 16;
    const int nc0  = jt * 64;

    const int  g4   = lane >> 2;
    const int  q    = lane & 3;
    const bool isev = (q & 1) == 0;

    // load weight slice (already tf32-rounded), float4
#pragma unroll 8
    for (int c = tid; c < 512 * 16; c += 128) {
        int k = c >> 4, c4 = c & 15;
        *(float4*)&Ws[k * WS_S + c4 * 4] =
            *(const float4*)&g_Wh[(size_t)k * NGATE + nc0 + c4 * 4];
    }
    // zero hs (t=0 state)
    for (int i = tid; i < 16 * HS_S; i += 128) hs[i] = 0.0f;
    // prefetch pre(0)
    {
        const float* pp = g_pre + (size_t)row0 * NGATE + nc0;
#pragma unroll
        for (int i = 0; i < 2; i++) {
            int c = i * 128 + tid;
            int r = c >> 4, c4 = c & 15;
            cp16(smem_u32(psm + r * PS_S + c4 * 4), pp + (size_t)r * NGATE + c4 * 4);
        }
    }
    CP_COMMIT();
    __syncthreads();

    unsigned* cnt = &g_cnt[bg * 32];
    float cst[2][2] = {{0.f, 0.f}, {0.f, 0.f}};

    for (int t = 0; t < SEQ; t++) {
        if (t > 0) {
            if (tid == 0) {
                unsigned v;
                const unsigned need = 32u * (unsigned)t;
                do {
                    asm volatile("ld.acquire.gpu.global.u32 %0, [%1];"
                                 : "=r"(v) : "l"(cnt) : "memory");
                } while (v < need);
            }
            __syncthreads();
            const float* hp = g_h[t & 1];
#pragma unroll
            for (int i = 0; i < 16; i++) {
                int c = i * 128 + tid;
                int r = c >> 7, c4 = c & 127;
                cp16(smem_u32(hs + r * HS_S + c4 * 4),
                     hp + (size_t)(row0 + r) * HID + c4 * 4);
            }
            CP_COMMIT();
        }
        cp_wait<0>();
        __syncthreads();

        float acc[2][4] = {{0.f, 0.f, 0.f, 0.f}, {0.f, 0.f, 0.f, 0.f}};
        const float* hrow0 = hs + g4 * HS_S + q;
        const float* hrow1 = hs + (g4 + 8) * HS_S + q;
        const float* wcol0 = Ws + (w * 16 + g4) + q * WS_S;
        const float* wcol1 = Ws + (w * 16 + 8 + g4) + q * WS_S;
#pragma unroll 16
        for (int kk = 0; kk < 64; kk++) {
            const int k = kk * 8;
            uint32_t a0 = __float_as_uint(hrow0[k]);
            uint32_t a1 = __float_as_uint(hrow1[k]);
            uint32_t a2 = __float_as_uint(hrow0[k + 4]);
            uint32_t a3 = __float_as_uint(hrow1[k + 4]);
            uint32_t b00 = __float_as_uint(wcol0[k * WS_S]);
            uint32_t b01 = __float_as_uint(wcol0[(k + 4) * WS_S]);
            uint32_t b10 = __float_as_uint(wcol1[k * WS_S]);
            uint32_t b11 = __float_as_uint(wcol1[(k + 4) * WS_S]);
            mma_tf32(acc[0], a0, a1, a2, a3, b00, b01);
            mma_tf32(acc[1], a0, a1, a2, a3, b10, b11);
        }

        // prefetch pre(t+1)
        if (t + 1 < SEQ) {
            const float* pp = g_pre + ((size_t)(t + 1) * BATCH + row0) * NGATE + nc0;
            float* pd = psm + ((t + 1) & 1) * 16 * PS_S;
#pragma unroll
            for (int i = 0; i < 2; i++) {
                int c = i * 128 + tid;
                int r = c >> 4, c4 = c & 15;
                cp16(smem_u32(pd + r * PS_S + c4 * 4), pp + (size_t)r * NGATE + c4 * 4);
            }
            CP_COMMIT();
        }

        // fused LSTM elementwise
        const float* ps = psm + (t & 1) * 16 * PS_S;
#pragma unroll
        for (int ni = 0; ni < 2; ni++) {
            int nl = w * 16 + ni * 8 + 2 * q;
            float v0 = acc[ni][0] + ps[g4 * PS_S + nl];
            float v1 = acc[ni][1] + ps[g4 * PS_S + nl + 1];
            float v2 = acc[ni][2] + ps[(g4 + 8) * PS_S + nl];
            float v3 = acc[ni][3] + ps[(g4 + 8) * PS_S + nl + 1];
            float e0 = isev ? sfast(v0) : tfast(v0);
            float e1 = sfast(v1);
            float e2 = isev ? sfast(v2) : tfast(v2);
            float e3 = sfast(v3);
            float p0 = __shfl_xor_sync(0xffffffffu, e0, 1);
            float p1 = __shfl_xor_sync(0xffffffffu, e1, 1);
            float p2 = __shfl_xor_sync(0xffffffffu, e2, 1);
            float p3 = __shfl_xor_sync(0xffffffffu, e3, 1);
            if (isev) {
                float c0 = e0 * cst[ni][0] + e1 * p0;
                float c1 = e2 * cst[ni][1] + e3 * p2;
                cst[ni][0] = c0;
                cst[ni][1] = c1;
                float h0 = p1 * tfast(c0);
                float h1 = p3 * tfast(c1);
                int jl = w * 4 + ni * 2 + (q >> 1);
                os[g4 * 17 + jl]       = h0;
                os[(g4 + 8) * 17 + jl] = h1;
            }
        }
        __syncthreads();

        // write out[t] and rounded h for next step
        {
            float* hn = g_h[(t + 1) & 1];
            float* op = out + ((size_t)t * BATCH + row0) * HID + jt * 16;
#pragma unroll
            for (int i = 0; i < 2; i++) {
                int c = i * 128 + tid;
                int r = c >> 4, j = c & 15;
                float v = os[r * 17 + j];
                op[(size_t)r * HID + j] = v;
                hn[(row0 + r) * HID + jt * 16 + j] = to_tf32(v);
            }
        }
        __threadfence();
        __syncthreads();
        if (tid == 0) {
            asm volatile("red.release.gpu.global.add.u32 [%0], %1;"
                         :: "l"(cnt), "r"(1u) : "memory");
        }
    }

    if (write_tail) {
        float* hx = out + (size_t)SEQ * BATCH * HID;
        float* cx = hx + BATCH * HID;
        for (int i = tid; i < 256; i += 128) {
            int r = i >> 4, j = i & 15;
            hx[(row0 + r) * HID + jt * 16 + j] = os[r * 17 + j];
        }
        __syncthreads();
#pragma unroll
        for (int ni = 0; ni < 2; ni++) {
            if (isev) {
                int jl = w * 4 + ni * 2 + (q >> 1);
                os[g4 * 17 + jl]       = cst[ni][0];
                os[(g4 + 8) * 17 + jl] = cst[ni][1];
            }
        }
        __syncthreads();
        for (int i = tid; i < 256; i += 128) {
            int r = i >> 4, j = i & 15;
            cx[(row0 + r) * HID + jt * 16 + j] = os[r * 17 + j];
        }
    }
}

// ---------------- launch ---------------------------------------------------
extern "C" void kernel_launch(void* const* d_in, const int* in_sizes, int n_in,
                              void* d_out, int out_size) {
    const float* X  = (const float*)d_in[0];
    const float* Wf = (const float*)d_in[1];
    const float* bf = (const float*)d_in[2];
    const float* Wi = (const float*)d_in[3];
    const float* bi = (const float*)d_in[4];
    const float* Wg = (const float*)d_in[5];
    const float* bg = (const float*)d_in[6];
    const float* Wo = (const float*)d_in[7];
    const float* bo = (const float*)d_in[8];
    float* out = (float*)d_out;

    reset_kernel<<<1, 128>>>();
    prep_kernel<<<((IN_DIM + HID) * HID + 255) / 256, 256>>>(Wf, bf, Wi, bi, Wg, bg, Wo, bo);
    roundx_kernel<<<4096, 256>>>(X);

    const int smem1 = (3 * GA_ST + 3 * GB_ST) * (int)sizeof(float);
    cudaFuncSetAttribute(gemm_pre_kernel, cudaFuncAttributeMaxDynamicSharedMemorySize, smem1);
    dim3 g1(NGATE / 128, SEQ * BATCH / 256);
    gemm_pre_kernel<<<g1, 256, smem1>>>();

    const int smem2 = (512 * WS_S + 16 * HS_S + 2 * 16 * PS_S + 16 * 17) * (int)sizeof(float);
    cudaFuncSetAttribute(lstm_rec_kernel, cudaFuncAttributeMaxDynamicSharedMemorySize, smem2);
    int tail = (out_size >= SEQ * BATCH * HID + 2 * BATCH * HID) ? 1 : 0;
    lstm_rec_kernel<<<128, 128, smem2>>>(out, tail);
}

// round 3
// speedup vs baseline: 3.4886x; 1.2416x over previous
#include <cuda_runtime.h>
#include <cuda_fp16.h>
#include <cstdint>

#define SEQ    2048
#define BATCH  64
#define IN_DIM 512
#define HID    512
#define NGATE  2048   // 4*HID, packed n = j*4 + gate (0=f,1=i,2=g,3=o)

// ---------------- device-global scratch ------------------------------------
__device__ __half g_Wxt[(size_t)NGATE * IN_DIM];          // [n][k] fp16, 2MB
__device__ __half g_Wht[(size_t)NGATE * HID];             // [n][k] fp16, 2MB
__device__ float  g_bias[NGATE];
__device__ __half g_Xh[(size_t)SEQ * BATCH * IN_DIM];     // 128MB fp16
__device__ __half g_pre[(size_t)SEQ * BATCH * NGATE];     // 512MB fp16
__device__ __half g_h[2][BATCH * HID];                    // fp16 h double buffer
__device__ unsigned g_cnt[4 * 32];                        // per-bg arrival counters

// ---------------- helpers --------------------------------------------------
__device__ __forceinline__ void mma_f16(float c[4],
                                        uint32_t a0, uint32_t a1, uint32_t a2, uint32_t a3,
                                        uint32_t b0, uint32_t b1) {
    asm("mma.sync.aligned.m16n8k16.row.col.f32.f16.f16.f32 "
        "{%0,%1,%2,%3}, {%4,%5,%6,%7}, {%8,%9}, {%0,%1,%2,%3};"
        : "+f"(c[0]), "+f"(c[1]), "+f"(c[2]), "+f"(c[3])
        : "r"(a0), "r"(a1), "r"(a2), "r"(a3), "r"(b0), "r"(b1));
}

__device__ __forceinline__ float tfast(float x) {
    float y;
    asm("tanh.approx.f32 %0, %1;" : "=f"(y) : "f"(x));
    return y;
}
__device__ __forceinline__ float sfast(float x) {
    return fmaf(tfast(x * 0.5f), 0.5f, 0.5f);
}

__device__ __forceinline__ uint32_t smem_u32(const void* p) {
    return (uint32_t)__cvta_generic_to_shared(p);
}
__device__ __forceinline__ void cp16(uint32_t dst, const void* src) {
    asm volatile("cp.async.cg.shared.global [%0], [%1], 16;" :: "r"(dst), "l"(src));
}
#define CP_COMMIT() asm volatile("cp.async.commit_group;")
template <int N>
__device__ __forceinline__ void cp_wait() {
    asm volatile("cp.async.wait_group %0;" :: "n"(N));
}

// ---------------- reset (per-launch) ---------------------------------------
__global__ void reset_kernel() {
    if (threadIdx.x < 4 * 32) g_cnt[threadIdx.x] = 0u;
}

// ---------------- prep: pack weights fp16, [n][k] transposed ----------------
__global__ void prep_kernel(const float* __restrict__ Wf, const float* __restrict__ bf,
                            const float* __restrict__ Wi, const float* __restrict__ bi,
                            const float* __restrict__ Wg, const float* __restrict__ bg,
                            const float* __restrict__ Wo, const float* __restrict__ bo) {
    int idx = blockIdx.x * blockDim.x + threadIdx.x;
    if (idx < (IN_DIM + HID) * HID) {
        int k = idx >> 9;
        int j = idx & 511;
        const float* Wlist[4] = {Wf, Wi, Wg, Wo};
#pragma unroll
        for (int g = 0; g < 4; g++) {
            __half w = __float2half(Wlist[g][(size_t)k * HID + j]);
            int n = j * 4 + g;
            if (k < IN_DIM) g_Wxt[(size_t)n * IN_DIM + k] = w;
            else            g_Wht[(size_t)n * HID + (k - IN_DIM)] = w;
        }
    }
    if (idx < HID) {
        const float* blist[4] = {bf, bi, bg, bo};
#pragma unroll
        for (int g = 0; g < 4; g++) g_bias[idx * 4 + g] = blist[g][idx];
    }
}

// ---------------- convert X to fp16 ----------------------------------------
__global__ void cvtx_kernel(const float* __restrict__ X) {
    const size_t n4 = (size_t)SEQ * BATCH * IN_DIM / 4;
    const float4* src = (const float4*)X;
    uint2* dst = (uint2*)g_Xh;
    for (size_t i = blockIdx.x * blockDim.x + threadIdx.x; i < n4;
         i += (size_t)gridDim.x * blockDim.x) {
        float4 v = src[i];
        __half2 h0 = __floats2half2_rn(v.x, v.y);
        __half2 h1 = __floats2half2_rn(v.z, v.w);
        uint2 u;
        u.x = *(uint32_t*)&h0;
        u.y = *(uint32_t*)&h1;
        dst[i] = u;
    }
}

// ---------------- phase 1: pre = Xh @ Wx + bias (fp16 mma, fp32 acc) -------
// CTA 256x128, BK=32, 3-stage cp.async, 8 warps (4m x 2n), warp 64x64.
#define GA_H (256 * 40)   // halves per A stage
#define GB_H (128 * 40)

__device__ __forceinline__ void gemm_load_stage(__half* As, __half* Bs,
                                                int m0, int n0, int kb, int tid) {
#pragma unroll
    for (int i = 0; i < 4; i++) {
        int c = i * 256 + tid;
        int row = c >> 2, seg = c & 3;
        cp16(smem_u32(As + row * 40 + seg * 8),
             g_Xh + (size_t)(m0 + row) * IN_DIM + kb + seg * 8);
    }
#pragma unroll
    for (int i = 0; i < 2; i++) {
        int c = i * 256 + tid;
        int col = c >> 2, seg = c & 3;
        cp16(smem_u32(Bs + col * 40 + seg * 8),
             g_Wxt + (size_t)(n0 + col) * IN_DIM + kb + seg * 8);
    }
}

__global__ __launch_bounds__(256, 1) void gemm_pre_kernel() {
    extern __shared__ __half smh[];
    __half* As[3] = {smh, smh + GA_H, smh + 2 * GA_H};
    __half* Bs[3] = {smh + 3 * GA_H, smh + 3 * GA_H + GB_H, smh + 3 * GA_H + 2 * GB_H};

    const int tid  = threadIdx.x;
    const int lane = tid & 31;
    const int warp = tid >> 5;
    const int g4   = lane >> 2;
    const int q    = lane & 3;
    const int m0 = blockIdx.y * 256;
    const int n0 = blockIdx.x * 128;   // n fast -> X reuse in L2
    const int wm = (warp >> 1) * 64;
    const int wn = (warp & 1) * 64;

    float acc[4][8][4];
#pragma unroll
    for (int mi = 0; mi < 4; mi++)
#pragma unroll
        for (int ni = 0; ni < 8; ni++)
#pragma unroll
            for (int l = 0; l < 4; l++) acc[mi][ni][l] = 0.0f;

    gemm_load_stage(As[0], Bs[0], m0, n0, 0, tid);  CP_COMMIT();
    gemm_load_stage(As[1], Bs[1], m0, n0, 32, tid); CP_COMMIT();

    for (int kt = 0; kt < 16; kt++) {
        if (kt + 2 < 16) {
            gemm_load_stage(As[(kt + 2) % 3], Bs[(kt + 2) % 3], m0, n0, (kt + 2) * 32, tid);
            CP_COMMIT();
        }
        if (kt <= 13)      cp_wait<2>();
        else if (kt == 14) cp_wait<1>();
        else               cp_wait<0>();
        __syncthreads();

        const __half* A = As[kt % 3];
        const __half* B = Bs[kt % 3];
#pragma unroll
        for (int ks = 0; ks < 2; ks++) {
            const int k = ks * 16;
            uint32_t a[4][4], b[8][2];
#pragma unroll
            for (int mi = 0; mi < 4; mi++) {
                int mr = wm + mi * 16 + g4;
                a[mi][0] = *(const uint32_t*)&A[mr * 40 + k + 2 * q];
                a[mi][1] = *(const uint32_t*)&A[(mr + 8) * 40 + k + 2 * q];
                a[mi][2] = *(const uint32_t*)&A[mr * 40 + k + 8 + 2 * q];
                a[mi][3] = *(const uint32_t*)&A[(mr + 8) * 40 + k + 8 + 2 * q];
            }
#pragma unroll
            for (int ni = 0; ni < 8; ni++) {
                int cn = wn + ni * 8 + g4;
                b[ni][0] = *(const uint32_t*)&B[cn * 40 + k + 2 * q];
                b[ni][1] = *(const uint32_t*)&B[cn * 40 + k + 8 + 2 * q];
            }
#pragma unroll
            for (int mi = 0; mi < 4; mi++)
#pragma unroll
                for (int ni = 0; ni < 8; ni++)
                    mma_f16(acc[mi][ni], a[mi][0], a[mi][1], a[mi][2], a[mi][3],
                            b[ni][0], b[ni][1]);
        }
        __syncthreads();
    }

    // epilogue: bias + fp16 store
#pragma unroll
    for (int mi = 0; mi < 4; mi++) {
        size_t r = (size_t)(m0 + wm + mi * 16 + g4);
#pragma unroll
        for (int ni = 0; ni < 8; ni++) {
            int c = n0 + wn + ni * 8 + 2 * q;
            float2 bb = *(const float2*)&g_bias[c];
            __half2 v0 = __floats2half2_rn(acc[mi][ni][0] + bb.x, acc[mi][ni][1] + bb.y);
            __half2 v1 = __floats2half2_rn(acc[mi][ni][2] + bb.x, acc[mi][ni][3] + bb.y);
            *(__half2*)&g_pre[r * NGATE + c]       = v0;
            *(__half2*)&g_pre[(r + 8) * NGATE + c] = v1;
        }
    }
}

// ---------------- phase 2: persistent recurrence (fp16 mma) ----------------
// 128 CTAs = 4 bg(16 batch rows) x 32 jt(64 gate-cols). Ws/hs/pre fp16 smem,
// chunked h staging overlapped with mma, per-bg counter sync, MUFU act.
#define HS_S 520   // halves
#define WS_S 520   // halves (per col)
#define PS_S 80    // halves
#define OS_S 18    // floats

__global__ __launch_bounds__(128, 1) void lstm_rec_kernel(float* __restrict__ out, int write_tail) {
    extern __shared__ char smc[];
    __half* Ws  = (__half*)smc;                 // [64 cols][520]
    __half* hs  = Ws + 64 * WS_S;               // [16 rows][520]
    __half* psm = hs + 16 * HS_S;               // [2][16][80]
    float*  os  = (float*)(psm + 2 * 16 * PS_S); // [16][18]

    const int tid  = threadIdx.x;
    const int lane = tid & 31;
    const int w    = tid >> 5;
    const int jt   = blockIdx.x & 31;
    const int bg   = blockIdx.x >> 5;
    const int row0 = bg * 16;
    const int nc0  = jt * 64;

    const int  g4   = lane >> 2;
    const int  q    = lane & 3;
    const bool isev = (q & 1) == 0;

    // load weight slice once (fp16, [col][k] contiguous)
    {
        const __half* wsrc = g_Wht + (size_t)nc0 * HID;
#pragma unroll 8
        for (int i = tid; i < 64 * 64; i += 128) {
            int c = i >> 6, s = i & 63;
            *(uint4*)&Ws[c * WS_S + s * 8] = *(const uint4*)&wsrc[(size_t)c * HID + s * 8];
        }
    }
    // zero hs (t=0 state)
    for (int i = tid; i < 16 * HS_S / 2; i += 128) ((uint32_t*)hs)[i] = 0u;
    // prefetch pre(0) into psm buffer 0 (1 cp16/thread)
    {
        const __half* pp = g_pre + (size_t)row0 * NGATE + nc0;
        int r = tid >> 3, s = tid & 7;
        cp16(smem_u32(psm + r * PS_S + s * 8), pp + (size_t)r * NGATE + s * 8);
    }
    CP_COMMIT();
    __syncthreads();

    unsigned* cnt = &g_cnt[bg * 32];
    float cst[2][2] = {{0.f, 0.f}, {0.f, 0.f}};

    const __half* hr0 = hs + g4 * HS_S;
    const __half* hr1 = hs + (g4 + 8) * HS_S;
    const __half* wc0 = Ws + (size_t)(w * 16 + g4) * WS_S;
    const __half* wc1 = Ws + (size_t)(w * 16 + 8 + g4) * WS_S;

    for (int t = 0; t < SEQ; t++) {
        float acc[2][4] = {{0.f, 0.f, 0.f, 0.f}, {0.f, 0.f, 0.f, 0.f}};

        auto mma_chunk = [&](int c) {
            const int base = c * 128;
#pragma unroll
            for (int kk = 0; kk < 8; kk++) {
                const int k = base + kk * 16;
                uint32_t a0 = *(const uint32_t*)&hr0[k + 2 * q];
                uint32_t a1 = *(const uint32_t*)&hr1[k + 2 * q];
                uint32_t a2 = *(const uint32_t*)&hr0[k + 8 + 2 * q];
                uint32_t a3 = *(const uint32_t*)&hr1[k + 8 + 2 * q];
                uint32_t b00 = *(const uint32_t*)&wc0[k + 2 * q];
                uint32_t b01 = *(const uint32_t*)&wc0[k + 8 + 2 * q];
                uint32_t b10 = *(const uint32_t*)&wc1[k + 2 * q];
                uint32_t b11 = *(const uint32_t*)&wc1[k + 8 + 2 * q];
                mma_f16(acc[0], a0, a1, a2, a3, b00, b01);
                mma_f16(acc[1], a0, a1, a2, a3, b10, b11);
            }
        };

        if (t > 0) {
            if (tid == 0) {
                unsigned v;
                const unsigned need = 32u * (unsigned)t;
                do {
                    asm volatile("ld.acquire.gpu.global.u32 %0, [%1];"
                                 : "=r"(v) : "l"(cnt) : "memory");
                } while (v < need);
            }
            __syncthreads();
            const __half* hp = g_h[t & 1];
#pragma unroll
            for (int c = 0; c < 4; c++) {
#pragma unroll
                for (int i = 0; i < 2; i++) {
                    int e = i * 128 + tid;
                    int r = e >> 4, s = e & 15;
                    cp16(smem_u32(hs + r * HS_S + c * 128 + s * 8),
                         hp + (size_t)(row0 + r) * HID + c * 128 + s * 8);
                }
                CP_COMMIT();
            }
            cp_wait<3>(); __syncthreads(); mma_chunk(0);
            cp_wait<2>(); __syncthreads(); mma_chunk(1);
            cp_wait<1>(); __syncthreads(); mma_chunk(2);
            cp_wait<0>(); __syncthreads(); mma_chunk(3);
        } else {
            cp_wait<0>();
            __syncthreads();
            mma_chunk(0); mma_chunk(1); mma_chunk(2); mma_chunk(3);
        }

        // fused LSTM elementwise
        const __half* ps = psm + (t & 1) * 16 * PS_S;
#pragma unroll
        for (int ni = 0; ni < 2; ni++) {
            int nl = w * 16 + ni * 8 + 2 * q;
            float v0 = acc[ni][0] + __half2float(ps[g4 * PS_S + nl]);
            float v1 = acc[ni][1] + __half2float(ps[g4 * PS_S + nl + 1]);
            float v2 = acc[ni][2] + __half2float(ps[(g4 + 8) * PS_S + nl]);
            float v3 = acc[ni][3] + __half2float(ps[(g4 + 8) * PS_S + nl + 1]);
            float e0 = isev ? sfast(v0) : tfast(v0);
            float e1 = sfast(v1);
            float e2 = isev ? sfast(v2) : tfast(v2);
            float e3 = sfast(v3);
            float p0 = __shfl_xor_sync(0xffffffffu, e0, 1);
            float p1 = __shfl_xor_sync(0xffffffffu, e1, 1);
            float p2 = __shfl_xor_sync(0xffffffffu, e2, 1);
            float p3 = __shfl_xor_sync(0xffffffffu, e3, 1);
            if (isev) {
                float c0 = e0 * cst[ni][0] + e1 * p0;   // f*c + i*g
                float c1 = e2 * cst[ni][1] + e3 * p2;
                cst[ni][0] = c0;
                cst[ni][1] = c1;
                float h0 = p1 * tfast(c0);              // o*tanh(c)
                float h1 = p3 * tfast(c1);
                int jl = w * 4 + ni * 2 + (q >> 1);
                os[g4 * OS_S + jl]       = h0;
                os[(g4 + 8) * OS_S + jl] = h1;
            }
        }
        __syncthreads();

        // write out[t] (fp32) and next h (fp16) — 1 vec store each per thread
        {
            __half* hn = g_h[(t + 1) & 1];
            float* op = out + ((size_t)t * BATCH + row0) * HID + jt * 16;
            int r = tid >> 3, p2 = (tid & 7) * 2;
            float2 v = *(float2*)&os[r * OS_S + p2];
            *(float2*)&op[(size_t)r * HID + p2] = v;
            *(__half2*)&hn[(size_t)(row0 + r) * HID + jt * 16 + p2] =
                __floats2half2_rn(v.x, v.y);
        }
        __threadfence();
        __syncthreads();
        if (tid == 0) {
            asm volatile("red.release.gpu.global.add.u32 [%0], %1;"
                         :: "l"(cnt), "r"(1u) : "memory");
        }

        // prefetch pre(t+1) into the other psm buffer
        if (t + 1 < SEQ) {
            const __half* pp = g_pre + ((size_t)(t + 1) * BATCH + row0) * NGATE + nc0;
            __half* pd = psm + ((t + 1) & 1) * 16 * PS_S;
            int r = tid >> 3, s = tid & 7;
            cp16(smem_u32(pd + r * PS_S + s * 8), pp + (size_t)r * NGATE + s * 8);
            CP_COMMIT();
        }
    }

    if (write_tail) {
        float* hx = out + (size_t)SEQ * BATCH * HID;
        float* cx = hx + BATCH * HID;
        for (int i = tid; i < 256; i += 128) {
            int r = i >> 4, j = i & 15;
            hx[(size_t)(row0 + r) * HID + jt * 16 + j] = os[r * OS_S + j];
        }
        __syncthreads();
#pragma unroll
        for (int ni = 0; ni < 2; ni++) {
            if (isev) {
                int jl = w * 4 + ni * 2 + (q >> 1);
                os[g4 * OS_S + jl]       = cst[ni][0];
                os[(g4 + 8) * OS_S + jl] = cst[ni][1];
            }
        }
        __syncthreads();
        for (int i = tid; i < 256; i += 128) {
            int r = i >> 4, j = i & 15;
            cx[(size_t)(row0 + r) * HID + jt * 16 + j] = os[r * OS_S + j];
        }
    }
}

// ---------------- launch ---------------------------------------------------
extern "C" void kernel_launch(void* const* d_in, const int* in_sizes, int n_in,
                              void* d_out, int out_size) {
    const float* X  = (const float*)d_in[0];
    const float* Wf = (const float*)d_in[1];
    const float* bf = (const float*)d_in[2];
    const float* Wi = (const float*)d_in[3];
    const float* bi = (const float*)d_in[4];
    const float* Wg = (const float*)d_in[5];
    const float* bg = (const float*)d_in[6];
    const float* Wo = (const float*)d_in[7];
    const float* bo = (const float*)d_in[8];
    float* out = (float*)d_out;

    reset_kernel<<<1, 128>>>();
    prep_kernel<<<((IN_DIM + HID) * HID + 255) / 256, 256>>>(Wf, bf, Wi, bi, Wg, bg, Wo, bo);
    cvtx_kernel<<<4096, 256>>>(X);

    const int smem1 = 3 * (GA_H + GB_H) * (int)sizeof(__half);
    cudaFuncSetAttribute(gemm_pre_kernel, cudaFuncAttributeMaxDynamicSharedMemorySize, smem1);
    dim3 g1(NGATE / 128, SEQ * BATCH / 256);
    gemm_pre_kernel<<<g1, 256, smem1>>>();

    const int smem2 = (64 * WS_S + 16 * HS_S + 2 * 16 * PS_S) * (int)sizeof(__half)
                    + 16 * OS_S * (int)sizeof(float);
    cudaFuncSetAttribute(lstm_rec_kernel, cudaFuncAttributeMaxDynamicSharedMemorySize, smem2);
    int tail = (out_size >= SEQ * BATCH * HID + 2 * BATCH * HID) ? 1 : 0;
    lstm_rec_kernel<<<128, 128, smem2>>>(out, tail);
}